// round 9
// baseline (speedup 1.0000x reference)
#include <cuda_runtime.h>
#include <cuda_fp16.h>
#include <cstdint>
#include <math.h>

#define B_    2
#define S_    2048
#define D_    1024
#define H_    16
#define NTOK  4096
#define E_    8
#define MROWS 9216
#define NTILES 72
#define M1Q   262144   // (1024*1024)/4 float4s per 1M-element matrix

#define ASTR 72
#define BSTR 136
#define GEMM_SMEM (3*(128*ASTR + 64*BSTR)*2)   // 107520 bytes

// ---------------- device scratch ----------------
__device__ float g_h  [NTOK*D_];
__device__ float g_xf [NTOK*D_];
__device__ float g_sh [NTOK*D_];
__device__ float g_eo [MROWS*D_];

__device__ __half g_qkvs[3*NTOK*D_];   // q | k | v (post-rope)
__device__ __half g_xnh [NTOK*D_];
__device__ __half g_atth[NTOK*D_];
__device__ __half g_xfh [NTOK*D_];
__device__ __half g_th  [NTOK*D_];
__device__ __half g_h1h [MROWS*D_];

__device__ __half g_wqkvh[D_*3072];
__device__ __half g_woh  [D_*D_];
__device__ __half g_w13h [D_*2048];        // interleaved sw1/sw3 columns
__device__ __half g_sw2h [D_*D_];
__device__ __half g_ew13h[E_*D_*2048];     // interleaved ew1/ew3 per expert
__device__ __half g_ew2h [E_*D_*D_];

__device__ int   g_counts [E_];
__device__ int   g_cursor [E_];
__device__ int   g_padbase[E_+1];
__device__ int   g_tileE  [NTILES];
__device__ int   g_gather [MROWS];
__device__ int   g_tokE   [NTOK*2];
__device__ float g_tokW   [NTOK*2];
__device__ int   g_tokPos [NTOK*2];

// ---------------- ptx helpers ----------------
__device__ __forceinline__ uint32_t sptr(const void* p){ return (uint32_t)__cvta_generic_to_shared(p); }
__device__ __forceinline__ void ldsm4(uint32_t* r, uint32_t a){
    asm volatile("ldmatrix.sync.aligned.m8n8.x4.shared.b16 {%0,%1,%2,%3},[%4];"
        :"=r"(r[0]),"=r"(r[1]),"=r"(r[2]),"=r"(r[3]):"r"(a));
}
__device__ __forceinline__ void ldsm4t(uint32_t* r, uint32_t a){
    asm volatile("ldmatrix.sync.aligned.m8n8.x4.trans.shared.b16 {%0,%1,%2,%3},[%4];"
        :"=r"(r[0]),"=r"(r[1]),"=r"(r[2]),"=r"(r[3]):"r"(a));
}
__device__ __forceinline__ void mma16816(float* c, const uint32_t* a, const uint32_t* b){
    asm volatile("mma.sync.aligned.m16n8k16.row.col.f32.f16.f16.f32 "
        "{%0,%1,%2,%3},{%4,%5,%6,%7},{%8,%9},{%0,%1,%2,%3};"
        :"+f"(c[0]),"+f"(c[1]),"+f"(c[2]),"+f"(c[3])
        :"r"(a[0]),"r"(a[1]),"r"(a[2]),"r"(a[3]),"r"(b[0]),"r"(b[1]));
}
__device__ __forceinline__ void cp16(uint32_t d, const void* s){
    asm volatile("cp.async.cg.shared.global [%0],[%1],16;"::"r"(d),"l"(s));
}
__device__ __forceinline__ void cpcommit(){ asm volatile("cp.async.commit_group;"); }
template<int N> __device__ __forceinline__ void cpwait(){ asm volatile("cp.async.wait_group %0;"::"n"(N)); }
__device__ __forceinline__ uint32_t packh2(float a, float b){
    __half2 h = __floats2half2_rn(a,b); return *(uint32_t*)&h;
}

// ---------------- merged weight conversion (fp32 -> fp16, with layout fusion) ----
__global__ __launch_bounds__(256) void cvtall_k(
    const float4* __restrict__ wq, const float4* __restrict__ wk, const float4* __restrict__ wv,
    const float4* __restrict__ wo, const float4* __restrict__ sw1,
    const float4* __restrict__ sw2, const float4* __restrict__ sw3,
    const float4* __restrict__ ew1, const float4* __restrict__ ew2, const float4* __restrict__ ew3)
{
    int i = blockIdx.x*256 + threadIdx.x;
    if (i < M1Q){
        float4 v = wo[i];
        uint2 p; p.x = packh2(v.x,v.y); p.y = packh2(v.z,v.w);
        *(uint2*)(g_woh + (long)i*4) = p;
    } else if (i < 2*M1Q){
        int t = i - M1Q;
        float4 v = sw2[t];
        uint2 p; p.x = packh2(v.x,v.y); p.y = packh2(v.z,v.w);
        *(uint2*)(g_sw2h + (long)t*4) = p;
    } else if (i < 3*M1Q){
        int t = i - 2*M1Q;
        long e4 = (long)t*4;
        float4 a = sw1[t], b = sw3[t];
        uint4 p; p.x = packh2(a.x,b.x); p.y = packh2(a.y,b.y);
        p.z = packh2(a.z,b.z); p.w = packh2(a.w,b.w);
        *(uint4*)(g_w13h + (e4>>10)*2048 + 2*(e4&1023)) = p;
    } else if (i < 11*M1Q){
        int t = i - 3*M1Q;
        float4 v = ew2[t];
        uint2 p; p.x = packh2(v.x,v.y); p.y = packh2(v.z,v.w);
        *(uint2*)(g_ew2h + (long)t*4) = p;
    } else if (i < 19*M1Q){
        int t = i - 11*M1Q;
        long e4 = (long)t*4;
        long ex = e4 >> 20;
        long rem = e4 & 1048575;
        float4 a = ew1[t], b = ew3[t];
        uint4 p; p.x = packh2(a.x,b.x); p.y = packh2(a.y,b.y);
        p.z = packh2(a.z,b.z); p.w = packh2(a.w,b.w);
        *(uint4*)(g_ew13h + ex*(1024l*2048) + (rem>>10)*2048 + 2*(rem&1023)) = p;
    } else {
        int j = i - 19*M1Q;
        int m = j >> 18, t = j & (M1Q-1);
        const float4* s = (m==0)? wq : (m==1)? wk : wv;
        float4 v = s[t];
        long e = (long)t*4;
        uint2 p; p.x = packh2(v.x,v.y); p.y = packh2(v.z,v.w);
        *(uint2*)(g_wqkvh + (e>>10)*3072 + m*1024 + (e&1023)) = p;
    }
}

// ---------------- rmsnorm ----------------
__global__ __launch_bounds__(256) void rmsnorm_k(const float* __restrict__ x, const float* __restrict__ w,
                                                 float* __restrict__ yf, __half* __restrict__ yh){
    int n = blockIdx.x;
    const float* xr = x + (long)n * D_;
    float v[4]; float ss = 0.f;
    #pragma unroll
    for (int u = 0; u < 4; u++){ v[u] = xr[threadIdx.x + u*256]; ss += v[u]*v[u]; }
    __shared__ float red[256];
    red[threadIdx.x] = ss; __syncthreads();
    for (int s = 128; s > 0; s >>= 1){
        if (threadIdx.x < s) red[threadIdx.x] += red[threadIdx.x + s];
        __syncthreads();
    }
    float r = rsqrtf(red[0] / (float)D_ + 1e-6f);
    #pragma unroll
    for (int u = 0; u < 4; u++){
        int c = threadIdx.x + u*256;
        float val = v[u]*r*w[c];
        yh[(long)n*D_ + c] = __float2half(val);
        if (yf) yf[(long)n*D_ + c] = val;
    }
}

// ---------------- HGEMM 128x128, K-chunk 64, 3-stage cp.async, mma.sync ------
// EPI: 0 C=acc(f32) ; 1 C=acc+C2 (f32) ; 3 fused silu-mul (half, N/2 wide) ;
//      4 fused rope qkv epilogue
template<typename OutT, int EPI>
__global__ __launch_bounds__(256) void hgemm_k(
    const __half* __restrict__ A, const __half* __restrict__ Bw,
    OutT* __restrict__ C, const float* __restrict__ C2,
    int K, int N,
    const int* __restrict__ gatherIdx, const int* __restrict__ tileExpert, long estride,
    const float* __restrict__ fcp, const float* __restrict__ fsp)
{
    extern __shared__ __half smem[];
    __half* As = smem;                    // 3 stages of 128*ASTR
    __half* Bs = smem + 3*128*ASTR;       // 3 stages of 64*BSTR
    const int tid = threadIdx.x, lane = tid & 31, wid = tid >> 5;
    const int wm = wid & 1, wn = wid >> 1;
    const int row0 = blockIdx.y*128, col0 = blockIdx.x*128;
    const __half* Bp = Bw + (tileExpert ? (long)tileExpert[blockIdx.y]*estride : 0);

    const int ar = tid >> 1, acb = (tid & 1)*32;   // A row, col base (32 cols per thread)
    long arow = 0; bool azero = false;
    if (gatherIdx){ int g = gatherIdx[row0 + ar]; if (g < 0) azero = true; else arow = (long)g*K; }
    else arow = (long)(row0 + ar)*K;
    const int br = tid >> 2, bcb = (tid & 3)*32;   // B row (0..63), col base

    float acc[4][4][4];
    #pragma unroll
    for (int a=0;a<4;a++)
        #pragma unroll
        for (int b=0;b<4;b++)
            #pragma unroll
            for (int c=0;c<4;c++) acc[a][b][c]=0.f;

    const int NIT = K >> 6;
    auto issue = [&](int it, int buf){
        int k0 = it << 6;
        __half* Ab = As + buf*128*ASTR;
        __half* Bb = Bs + buf*64*BSTR;
        if (azero){
            #pragma unroll
            for (int j = 0; j < 4; j++)
                *(uint4*)(&Ab[ar*ASTR + acb + j*8]) = make_uint4(0,0,0,0);
        } else {
            #pragma unroll
            for (int j = 0; j < 4; j++)
                cp16(sptr(&Ab[ar*ASTR + acb + j*8]), A + arow + k0 + acb + j*8);
        }
        #pragma unroll
        for (int j = 0; j < 4; j++)
            cp16(sptr(&Bb[br*BSTR + bcb + j*8]), Bp + (long)(k0 + br)*N + col0 + bcb + j*8);
    };

    issue(0,0); cpcommit();
    issue(1,1); cpcommit();
    int cur = 0;
    for (int it = 0; it < NIT; ++it){
        cpwait<1>(); __syncthreads();
        if (it+2 < NIT){ issue(it+2, (it+2)%3); cpcommit(); }
        __half* Ab = As + cur*128*ASTR;
        __half* Bb = Bs + cur*64*BSTR;
        #pragma unroll
        for (int ks = 0; ks < 4; ++ks){
            uint32_t af[4][4];
            #pragma unroll
            for (int mf = 0; mf < 4; ++mf)
                ldsm4(af[mf], sptr(&Ab[(wm*64 + mf*16 + (lane&15))*ASTR + ks*16 + (lane>>4)*8]));
            uint32_t bf[4][2];
            #pragma unroll
            for (int nf2 = 0; nf2 < 2; ++nf2){
                uint32_t r[4];
                ldsm4t(r, sptr(&Bb[(ks*16 + (lane&15))*BSTR + wn*32 + nf2*16 + (lane>>4)*8]));
                bf[nf2*2][0]=r[0]; bf[nf2*2][1]=r[1]; bf[nf2*2+1][0]=r[2]; bf[nf2*2+1][1]=r[3];
            }
            #pragma unroll
            for (int mf = 0; mf < 4; ++mf)
                #pragma unroll
                for (int nt = 0; nt < 4; ++nt)
                    mma16816(acc[mf][nt], af[mf], bf[nt]);
        }
        cur = (cur+1)%3;
    }

    #pragma unroll
    for (int mf = 0; mf < 4; ++mf){
        int rbase = row0 + wm*64 + mf*16 + (lane>>2);
        #pragma unroll
        for (int nt = 0; nt < 4; ++nt){
            int c = col0 + wn*32 + nt*8 + (lane&3)*2;
            #pragma unroll
            for (int hh = 0; hh < 2; ++hh){
                int rr = rbase + hh*8;
                float v0 = acc[mf][nt][hh*2], v1 = acc[mf][nt][hh*2+1];
                if (EPI == 0){
                    float2 w2; w2.x = v0; w2.y = v1;
                    *(float2*)((float*)C + (long)rr*N + c) = w2;
                } else if (EPI == 1){
                    float2 rr2 = *(const float2*)(C2 + (long)rr*N + c);
                    float2 w2; w2.x = v0 + rr2.x; w2.y = v1 + rr2.y;
                    *(float2*)((float*)C + (long)rr*N + c) = w2;
                } else if (EPI == 3){
                    float sv = v0 / (1.f + __expf(-v0)) * v1;
                    ((__half*)C)[(long)rr*(N>>1) + (c>>1)] = __float2half(sv);
                } else { // EPI == 4: rope + split to q|k|v
                    __half* base = (__half*)C;
                    int cc_ = c;
                    if (c >= 2048){ base += 2l*NTOK*D_; cc_ = c - 2048; }
                    else if (c >= 1024){ base += (long)NTOK*D_; cc_ = c - 1024; }
                    if (c < 2048){
                        int s = rr & (S_-1);
                        int fi = (cc_ & 63) >> 1;
                        float co = fcp[s*32+fi], sn = fsp[s*32+fi];
                        *(__half2*)(base + (long)rr*D_ + cc_) =
                            __floats2half2_rn(v0*co - v1*sn, v0*sn + v1*co);
                    } else {
                        *(__half2*)(base + (long)rr*D_ + cc_) = __floats2half2_rn(v0, v1);
                    }
                }
            }
        }
    }
}

// ---------------- flash attention fp16 (FA2-style), 64 q-rows / block --------
__global__ __launch_bounds__(128) void flash_h_k(const __half* __restrict__ qh, const __half* __restrict__ kh,
                                                 const __half* __restrict__ vh, __half* __restrict__ o){
    __shared__ __half Qs[64*72];
    __shared__ __half Ks[2][64*72];
    __shared__ __half Vs[2][64*72];
    const int tid = threadIdx.x, lane = tid & 31, w = tid >> 5;
    const int bh = blockIdx.y, b = bh >> 4, h = bh & 15;
    const int q0 = blockIdx.x*64;
    const int lrow = tid >> 1, lc0 = (tid & 1)*4;

    {
        const __half* qb = qh + ((long)b*S_ + q0 + lrow)*D_ + h*64;
        #pragma unroll
        for (int c = 0; c < 4; c++)
            cp16(sptr(&Qs[lrow*72 + (lc0 + c)*8]), qb + (lc0 + c)*8);
        cpcommit();
    }
    auto issue_kv = [&](int kt, int buf){
        const __half* kb = kh + ((long)b*S_ + kt + lrow)*D_ + h*64;
        const __half* vb = vh + ((long)b*S_ + kt + lrow)*D_ + h*64;
        #pragma unroll
        for (int c = 0; c < 4; c++){
            cp16(sptr(&Ks[buf][lrow*72 + (lc0 + c)*8]), kb + (lc0 + c)*8);
            cp16(sptr(&Vs[buf][lrow*72 + (lc0 + c)*8]), vb + (lc0 + c)*8);
        }
    };
    issue_kv(0, 0); cpcommit();

    cpwait<1>(); __syncthreads();
    uint32_t aQ[4][4];
    #pragma unroll
    for (int ks = 0; ks < 4; ks++)
        ldsm4(aQ[ks], sptr(&Qs[(w*16 + (lane&15))*72 + ks*16 + (lane>>4)*8]));

    float oa[8][4];
    #pragma unroll
    for (int i = 0; i < 8; i++){ oa[i][0]=0.f; oa[i][1]=0.f; oa[i][2]=0.f; oa[i][3]=0.f; }
    float m0 = -1e30f, m1 = -1e30f, l0 = 0.f, l1 = 0.f;

    const int NKT = S_/64;
    for (int kti = 0; kti < NKT; ++kti){
        int cur = kti & 1;
        cpwait<0>(); __syncthreads();
        if (kti+1 < NKT){ issue_kv((kti+1)*64, cur^1); cpcommit(); }

        float sa[8][4];
        #pragma unroll
        for (int i = 0; i < 8; i++){ sa[i][0]=0.f; sa[i][1]=0.f; sa[i][2]=0.f; sa[i][3]=0.f; }
        #pragma unroll
        for (int ks = 0; ks < 4; ++ks){
            #pragma unroll
            for (int nf2 = 0; nf2 < 4; ++nf2){
                uint32_t r[4];
                ldsm4(r, sptr(&Ks[cur][(nf2*16 + (lane&15))*72 + ks*16 + (lane>>4)*8]));
                uint32_t blo[2] = {r[0], r[2]}, bhi[2] = {r[1], r[3]};
                mma16816(sa[nf2*2],   aQ[ks], blo);
                mma16816(sa[nf2*2+1], aQ[ks], bhi);
            }
        }
        float cm0 = -1e30f, cm1 = -1e30f;
        #pragma unroll
        for (int nt = 0; nt < 8; ++nt){
            sa[nt][0]*=0.125f; sa[nt][1]*=0.125f; sa[nt][2]*=0.125f; sa[nt][3]*=0.125f;
            cm0 = fmaxf(cm0, fmaxf(sa[nt][0], sa[nt][1]));
            cm1 = fmaxf(cm1, fmaxf(sa[nt][2], sa[nt][3]));
        }
        cm0 = fmaxf(cm0, __shfl_xor_sync(0xffffffffu, cm0, 1));
        cm0 = fmaxf(cm0, __shfl_xor_sync(0xffffffffu, cm0, 2));
        cm1 = fmaxf(cm1, __shfl_xor_sync(0xffffffffu, cm1, 1));
        cm1 = fmaxf(cm1, __shfl_xor_sync(0xffffffffu, cm1, 2));
        float nm0 = fmaxf(m0, cm0), nm1 = fmaxf(m1, cm1);
        float a0 = __expf(m0 - nm0), a1 = __expf(m1 - nm1);
        float rs0 = 0.f, rs1 = 0.f;
        #pragma unroll
        for (int nt = 0; nt < 8; ++nt){
            sa[nt][0] = __expf(sa[nt][0] - nm0); rs0 += sa[nt][0];
            sa[nt][1] = __expf(sa[nt][1] - nm0); rs0 += sa[nt][1];
            sa[nt][2] = __expf(sa[nt][2] - nm1); rs1 += sa[nt][2];
            sa[nt][3] = __expf(sa[nt][3] - nm1); rs1 += sa[nt][3];
        }
        rs0 += __shfl_xor_sync(0xffffffffu, rs0, 1);
        rs0 += __shfl_xor_sync(0xffffffffu, rs0, 2);
        rs1 += __shfl_xor_sync(0xffffffffu, rs1, 1);
        rs1 += __shfl_xor_sync(0xffffffffu, rs1, 2);
        l0 = l0*a0 + rs0; l1 = l1*a1 + rs1; m0 = nm0; m1 = nm1;
        #pragma unroll
        for (int nt = 0; nt < 8; ++nt){ oa[nt][0]*=a0; oa[nt][1]*=a0; oa[nt][2]*=a1; oa[nt][3]*=a1; }
        uint32_t pa[4][4];
        #pragma unroll
        for (int kf = 0; kf < 4; ++kf){
            pa[kf][0] = packh2(sa[2*kf][0],   sa[2*kf][1]);
            pa[kf][1] = packh2(sa[2*kf][2],   sa[2*kf][3]);
            pa[kf][2] = packh2(sa[2*kf+1][0], sa[2*kf+1][1]);
            pa[kf][3] = packh2(sa[2*kf+1][2], sa[2*kf+1][3]);
        }
        #pragma unroll
        for (int kf = 0; kf < 4; ++kf){
            #pragma unroll
            for (int nf2 = 0; nf2 < 4; ++nf2){
                uint32_t r[4];
                ldsm4t(r, sptr(&Vs[cur][(kf*16 + (lane&15))*72 + nf2*16 + (lane>>4)*8]));
                uint32_t blo[2] = {r[0], r[1]}, bhi[2] = {r[2], r[3]};
                mma16816(oa[nf2*2],   pa[kf], blo);
                mma16816(oa[nf2*2+1], pa[kf], bhi);
            }
        }
    }

    float il0 = 1.f / l0, il1 = 1.f / l1;
    int rlo = q0 + w*16 + (lane>>2);
    #pragma unroll
    for (int nt = 0; nt < 8; ++nt){
        int c = h*64 + nt*8 + (lane&3)*2;
        *(__half2*)(o + ((long)b*S_ + rlo)*D_ + c)     = __floats2half2_rn(oa[nt][0]*il0, oa[nt][1]*il0);
        *(__half2*)(o + ((long)b*S_ + rlo + 8)*D_ + c) = __floats2half2_rn(oa[nt][2]*il1, oa[nt][3]*il1);
    }
}

// ---------------- MoE routing ----------------
__global__ __launch_bounds__(256) void moe_init_k(){
    int i = blockIdx.x*256 + threadIdx.x;
    if (i < MROWS) g_gather[i] = -1;
    if (i < E_){ g_counts[i] = 0; g_cursor[i] = 0; }
}

__global__ __launch_bounds__(256) void gate_k(const float* __restrict__ xf, const float* __restrict__ gw){
    int n = blockIdx.x;
    int tid = threadIdx.x, w = tid >> 5, lane = tid & 31;
    const float* xr = xf + (long)n * D_;
    const float* gr = gw + (long)w * D_;
    float s = 0.f;
    for (int d = lane; d < D_; d += 32) s += xr[d] * gr[d];
    #pragma unroll
    for (int o = 16; o; o >>= 1) s += __shfl_xor_sync(0xffffffffu, s, o);
    __shared__ float sc[E_];
    if (lane == 0) sc[w] = s;
    __syncthreads();
    if (tid == 0){
        float mx = sc[0];
        for (int e = 1; e < E_; e++) mx = fmaxf(mx, sc[e]);
        float p[E_]; float sum = 0.f;
        for (int e = 0; e < E_; e++){ p[e] = expf(sc[e] - mx); sum += p[e]; }
        float inv = 1.f / sum;
        for (int e = 0; e < E_; e++) p[e] *= inv;
        int e0 = 0;
        for (int e = 1; e < E_; e++) if (p[e] > p[e0]) e0 = e;
        int e1 = (e0 == 0) ? 1 : 0;
        for (int e = 0; e < E_; e++){ if (e == e0) continue; if (p[e] > p[e1]) e1 = e; }
        float v0 = p[e0], v1 = p[e1];
        float wi = 1.f / (v0 + v1 + 1e-9f);
        g_tokE[2*n] = e0; g_tokE[2*n+1] = e1;
        g_tokW[2*n] = v0*wi; g_tokW[2*n+1] = v1*wi;
        atomicAdd(&g_counts[e0], 1);
        atomicAdd(&g_counts[e1], 1);
    }
}

__global__ void offsets_k(){
    if (threadIdx.x == 0){
        int acc = 0;
        for (int e = 0; e < E_; e++){ g_padbase[e] = acc; acc += ((g_counts[e] + 127) >> 7) << 7; }
        g_padbase[E_] = acc;
    }
    __syncthreads();
    int t = threadIdx.x;
    if (t < NTILES){
        int start = t*128, te = 0;
        if (start < g_padbase[E_]){
            for (int e = 0; e < E_; e++)
                if (start >= g_padbase[e] && start < g_padbase[e+1]) te = e;
        }
        g_tileE[t] = te;
    }
}

__global__ __launch_bounds__(256) void scatter_k(){
    int n = blockIdx.x*256 + threadIdx.x;
    if (n >= NTOK) return;
    #pragma unroll
    for (int kk = 0; kk < 2; kk++){
        int e = g_tokE[2*n + kk];
        int slot = atomicAdd(&g_cursor[e], 1);
        int pos = g_padbase[e] + slot;
        g_gather[pos] = n;
        g_tokPos[2*n + kk] = pos;
    }
}

__global__ __launch_bounds__(256) void combine_k(float* __restrict__ out){
    int i = blockIdx.x*256 + threadIdx.x;
    int n = i >> 10, d = i & 1023;
    float v = g_h[i] + g_sh[i];
    v += g_tokW[2*n]   * g_eo[(long)g_tokPos[2*n]  * D_ + d];
    v += g_tokW[2*n+1] * g_eo[(long)g_tokPos[2*n+1]* D_ + d];
    out[i] = v;
}

// ---------------- host orchestration ----------------
extern "C" void kernel_launch(void* const* d_in, const int* in_sizes, int n_in,
                              void* d_out, int out_size) {
    const float* x   = (const float*)d_in[0];
    const float* fc  = (const float*)d_in[1];
    const float* fs  = (const float*)d_in[2];
    const float* anw = (const float*)d_in[3];
    const float* fnw = (const float*)d_in[4];
    const float* wq  = (const float*)d_in[5];
    const float* wk  = (const float*)d_in[6];
    const float* wv  = (const float*)d_in[7];
    const float* wo  = (const float*)d_in[8];
    const float* gw  = (const float*)d_in[9];
    const float* ew1 = (const float*)d_in[10];
    const float* ew2 = (const float*)d_in[11];
    const float* ew3 = (const float*)d_in[12];
    const float* sw1 = (const float*)d_in[13];
    const float* sw2 = (const float*)d_in[14];
    const float* sw3 = (const float*)d_in[15];
    float* out = (float*)d_out;

    float *h,*xf,*sh,*eo;
    __half *qkvs,*xnh,*atth,*xfh,*th,*h1h;
    __half *wqkvh,*woh,*w13h,*sw2h,*ew13h,*ew2h;
    int *gath,*tileE;
    cudaGetSymbolAddress((void**)&h,    g_h);
    cudaGetSymbolAddress((void**)&xf,   g_xf);
    cudaGetSymbolAddress((void**)&sh,   g_sh);
    cudaGetSymbolAddress((void**)&eo,   g_eo);
    cudaGetSymbolAddress((void**)&qkvs, g_qkvs);
    cudaGetSymbolAddress((void**)&xnh,  g_xnh);
    cudaGetSymbolAddress((void**)&atth, g_atth);
    cudaGetSymbolAddress((void**)&xfh,  g_xfh);
    cudaGetSymbolAddress((void**)&th,   g_th);
    cudaGetSymbolAddress((void**)&h1h,  g_h1h);
    cudaGetSymbolAddress((void**)&wqkvh,g_wqkvh);
    cudaGetSymbolAddress((void**)&woh,  g_woh);
    cudaGetSymbolAddress((void**)&w13h, g_w13h);
    cudaGetSymbolAddress((void**)&sw2h, g_sw2h);
    cudaGetSymbolAddress((void**)&ew13h,g_ew13h);
    cudaGetSymbolAddress((void**)&ew2h, g_ew2h);
    cudaGetSymbolAddress((void**)&gath,  g_gather);
    cudaGetSymbolAddress((void**)&tileE, g_tileE);

    __half* qh = qkvs;
    __half* kh = qkvs + (long)NTOK*D_;
    __half* vh = qkvs + 2l*NTOK*D_;

    cudaFuncSetAttribute(hgemm_k<float,0>,  cudaFuncAttributeMaxDynamicSharedMemorySize, GEMM_SMEM);
    cudaFuncSetAttribute(hgemm_k<float,1>,  cudaFuncAttributeMaxDynamicSharedMemorySize, GEMM_SMEM);
    cudaFuncSetAttribute(hgemm_k<__half,3>, cudaFuncAttributeMaxDynamicSharedMemorySize, GEMM_SMEM);
    cudaFuncSetAttribute(hgemm_k<__half,4>, cudaFuncAttributeMaxDynamicSharedMemorySize, GEMM_SMEM);

    // 0: merged weight conversion
    cvtall_k<<<(22*M1Q)/256, 256>>>(
        (const float4*)wq, (const float4*)wk, (const float4*)wv,
        (const float4*)wo, (const float4*)sw1, (const float4*)sw2, (const float4*)sw3,
        (const float4*)ew1, (const float4*)ew2, (const float4*)ew3);
    // 1: moe init
    moe_init_k<<<(MROWS + 255)/256, 256>>>();
    // 2: rmsnorm -> xnh
    rmsnorm_k<<<NTOK, 256>>>(x, anw, nullptr, xnh);
    // 3: QKV gemm + fused rope
    hgemm_k<__half,4><<<dim3(24,32), 256, GEMM_SMEM>>>(xnh, wqkvh, qkvs, nullptr, 1024, 3072,
                                                       nullptr, nullptr, 0, fc, fs);
    // 4: flash attention
    flash_h_k<<<dim3(S_/64, B_*H_), 128>>>(qh, kh, vh, atth);
    // 5: wo projection + residual  (<- ncu -s 5)
    hgemm_k<float,1><<<dim3(8,32), 256, GEMM_SMEM>>>(atth, woh, h, x, 1024, 1024,
                                                     nullptr, nullptr, 0, nullptr, nullptr);
    // 6: rmsnorm -> xf, xfh
    rmsnorm_k<<<NTOK, 256>>>(h, fnw, xf, xfh);
    // 7: fused shared FFN up
    hgemm_k<__half,3><<<dim3(16,32), 256, GEMM_SMEM>>>(xfh, w13h, th, nullptr, 1024, 2048,
                                                       nullptr, nullptr, 0, nullptr, nullptr);
    // 8: shared FFN down
    hgemm_k<float,0><<<dim3(8,32), 256, GEMM_SMEM>>>(th, sw2h, sh, nullptr, 1024, 1024,
                                                     nullptr, nullptr, 0, nullptr, nullptr);
    // 9-11: routing
    gate_k<<<NTOK, 256>>>(xf, gw);
    offsets_k<<<1, 128>>>();
    scatter_k<<<NTOK/256, 256>>>();
    // 12: fused MoE up (gathered)
    hgemm_k<__half,3><<<dim3(16,NTILES), 256, GEMM_SMEM>>>(xfh, ew13h, h1h, nullptr, 1024, 2048,
                                                           gath, tileE, 1024l*2048, nullptr, nullptr);
    // 13: MoE down
    hgemm_k<float,0><<<dim3(8,NTILES), 256, GEMM_SMEM>>>(h1h, ew2h, eo, nullptr, 1024, 1024,
                                                         nullptr, tileE, 1024l*1024, nullptr, nullptr);
    // 14: combine
    combine_k<<<(NTOK*D_)/256, 256>>>(out);
}

// round 11
// speedup vs baseline: 1.0028x; 1.0028x over previous
#include <cuda_runtime.h>
#include <cuda_fp16.h>
#include <cstdint>
#include <math.h>

#define B_    2
#define S_    2048
#define D_    1024
#define H_    16
#define NTOK  4096
#define E_    8
#define MROWS 9216
#define NTILES 72
#define M1Q   262144   // (1024*1024)/4 float4s per 1M-element matrix

#define ASTR 40
#define BSTR 264
#define GEMM_SMEM (3*(128*ASTR + 32*BSTR)*2)   // 81408 bytes

// ---------------- device scratch ----------------
__device__ float g_h  [NTOK*D_];
__device__ float g_xf [NTOK*D_];
__device__ float g_sh [NTOK*D_];
__device__ float g_eo [MROWS*D_];

__device__ __half g_qkvs[3*NTOK*D_];   // q | k | v (post-rope)
__device__ __half g_xnh [NTOK*D_];
__device__ __half g_atth[NTOK*D_];
__device__ __half g_xfh [NTOK*D_];
__device__ __half g_th  [NTOK*D_];
__device__ __half g_h1h [MROWS*D_];

__device__ __half g_wqkvh[D_*3072];
__device__ __half g_woh  [D_*D_];
__device__ __half g_w13h [D_*2048];        // interleaved sw1/sw3 columns
__device__ __half g_sw2h [D_*D_];
__device__ __half g_ew13h[E_*D_*2048];     // interleaved ew1/ew3 per expert
__device__ __half g_ew2h [E_*D_*D_];

__device__ int   g_counts [E_];
__device__ int   g_cursor [E_];
__device__ int   g_padbase[E_+1];
__device__ int   g_tileE  [NTILES];
__device__ int   g_gather [MROWS];
__device__ int   g_tokE   [NTOK*2];
__device__ float g_tokW   [NTOK*2];
__device__ int   g_tokPos [NTOK*2];

// ---------------- ptx helpers ----------------
__device__ __forceinline__ uint32_t sptr(const void* p){ return (uint32_t)__cvta_generic_to_shared(p); }
__device__ __forceinline__ void ldsm4(uint32_t* r, uint32_t a){
    asm volatile("ldmatrix.sync.aligned.m8n8.x4.shared.b16 {%0,%1,%2,%3},[%4];"
        :"=r"(r[0]),"=r"(r[1]),"=r"(r[2]),"=r"(r[3]):"r"(a));
}
__device__ __forceinline__ void ldsm4t(uint32_t* r, uint32_t a){
    asm volatile("ldmatrix.sync.aligned.m8n8.x4.trans.shared.b16 {%0,%1,%2,%3},[%4];"
        :"=r"(r[0]),"=r"(r[1]),"=r"(r[2]),"=r"(r[3]):"r"(a));
}
__device__ __forceinline__ void mma16816(float* c, const uint32_t* a, const uint32_t* b){
    asm volatile("mma.sync.aligned.m16n8k16.row.col.f32.f16.f16.f32 "
        "{%0,%1,%2,%3},{%4,%5,%6,%7},{%8,%9},{%0,%1,%2,%3};"
        :"+f"(c[0]),"+f"(c[1]),"+f"(c[2]),"+f"(c[3])
        :"r"(a[0]),"r"(a[1]),"r"(a[2]),"r"(a[3]),"r"(b[0]),"r"(b[1]));
}
__device__ __forceinline__ void cp16(uint32_t d, const void* s){
    asm volatile("cp.async.cg.shared.global [%0],[%1],16;"::"r"(d),"l"(s));
}
__device__ __forceinline__ void cpcommit(){ asm volatile("cp.async.commit_group;"); }
template<int N> __device__ __forceinline__ void cpwait(){ asm volatile("cp.async.wait_group %0;"::"n"(N)); }
__device__ __forceinline__ uint32_t packh2(float a, float b){
    __half2 h = __floats2half2_rn(a,b); return *(uint32_t*)&h;
}

// ---------------- merged weight conversion (fp32 -> fp16, with layout fusion) ----
__global__ __launch_bounds__(256) void cvtall_k(
    const float4* __restrict__ wq, const float4* __restrict__ wk, const float4* __restrict__ wv,
    const float4* __restrict__ wo, const float4* __restrict__ sw1,
    const float4* __restrict__ sw2, const float4* __restrict__ sw3,
    const float4* __restrict__ ew1, const float4* __restrict__ ew2, const float4* __restrict__ ew3)
{
    int i = blockIdx.x*256 + threadIdx.x;
    if (i < M1Q){
        float4 v = wo[i];
        uint2 p; p.x = packh2(v.x,v.y); p.y = packh2(v.z,v.w);
        *(uint2*)(g_woh + (long)i*4) = p;
    } else if (i < 2*M1Q){
        int t = i - M1Q;
        float4 v = sw2[t];
        uint2 p; p.x = packh2(v.x,v.y); p.y = packh2(v.z,v.w);
        *(uint2*)(g_sw2h + (long)t*4) = p;
    } else if (i < 3*M1Q){
        int t = i - 2*M1Q;
        long e4 = (long)t*4;
        float4 a = sw1[t], b = sw3[t];
        uint4 p; p.x = packh2(a.x,b.x); p.y = packh2(a.y,b.y);
        p.z = packh2(a.z,b.z); p.w = packh2(a.w,b.w);
        *(uint4*)(g_w13h + (e4>>10)*2048 + 2*(e4&1023)) = p;
    } else if (i < 11*M1Q){
        int t = i - 3*M1Q;
        float4 v = ew2[t];
        uint2 p; p.x = packh2(v.x,v.y); p.y = packh2(v.z,v.w);
        *(uint2*)(g_ew2h + (long)t*4) = p;
    } else if (i < 19*M1Q){
        int t = i - 11*M1Q;
        long e4 = (long)t*4;
        long ex = e4 >> 20;
        long rem = e4 & 1048575;
        float4 a = ew1[t], b = ew3[t];
        uint4 p; p.x = packh2(a.x,b.x); p.y = packh2(a.y,b.y);
        p.z = packh2(a.z,b.z); p.w = packh2(a.w,b.w);
        *(uint4*)(g_ew13h + ex*(1024l*2048) + (rem>>10)*2048 + 2*(rem&1023)) = p;
    } else {
        int j = i - 19*M1Q;
        int m = j >> 18, t = j & (M1Q-1);
        const float4* s = (m==0)? wq : (m==1)? wk : wv;
        float4 v = s[t];
        long e = (long)t*4;
        uint2 p; p.x = packh2(v.x,v.y); p.y = packh2(v.z,v.w);
        *(uint2*)(g_wqkvh + (e>>10)*3072 + m*1024 + (e&1023)) = p;
    }
}

// ---------------- rmsnorm ----------------
__global__ __launch_bounds__(256) void rmsnorm_k(const float* __restrict__ x, const float* __restrict__ w,
                                                 float* __restrict__ yf, __half* __restrict__ yh){
    int n = blockIdx.x;
    const float* xr = x + (long)n * D_;
    float v[4]; float ss = 0.f;
    #pragma unroll
    for (int u = 0; u < 4; u++){ v[u] = xr[threadIdx.x + u*256]; ss += v[u]*v[u]; }
    __shared__ float red[256];
    red[threadIdx.x] = ss; __syncthreads();
    for (int s = 128; s > 0; s >>= 1){
        if (threadIdx.x < s) red[threadIdx.x] += red[threadIdx.x + s];
        __syncthreads();
    }
    float r = rsqrtf(red[0] / (float)D_ + 1e-6f);
    #pragma unroll
    for (int u = 0; u < 4; u++){
        int c = threadIdx.x + u*256;
        float val = v[u]*r*w[c];
        yh[(long)n*D_ + c] = __float2half(val);
        if (yf) yf[(long)n*D_ + c] = val;
    }
}

// ---------------- HGEMM 128x256 CTA tile, 64x64 warp tile, K32 chunks --------
// EPI: 0 C=acc(f32) ; 1 C=acc+C2 (f32) ; 3 fused silu-mul (half, N/2 wide) ;
//      4 fused rope qkv epilogue
template<typename OutT, int EPI>
__global__ __launch_bounds__(256) void hgemm_k(
    const __half* __restrict__ A, const __half* __restrict__ Bw,
    OutT* __restrict__ C, const float* __restrict__ C2,
    int K, int N,
    const int* __restrict__ gatherIdx, const int* __restrict__ tileExpert, long estride,
    const float* __restrict__ fcp, const float* __restrict__ fsp)
{
    extern __shared__ __half smem[];
    __half* As = smem;                    // 3 stages of 128*ASTR
    __half* Bs = smem + 3*128*ASTR;       // 3 stages of 32*BSTR
    const int tid = threadIdx.x, lane = tid & 31, wid = tid >> 5;
    const int wm = wid & 1, wn = wid >> 1;      // warp tile: 64 rows x 64 cols
    const int row0 = blockIdx.y*128, col0 = blockIdx.x*256;
    const __half* Bp = Bw + (tileExpert ? (long)tileExpert[blockIdx.y]*estride : 0);

    const int ar = tid >> 1, ac = (tid & 1)*16;   // A: 2 cp16 per thread
    long arow = 0; bool azero = false;
    if (gatherIdx){ int g = gatherIdx[row0 + ar]; if (g < 0) azero = true; else arow = (long)g*K; }
    else arow = (long)(row0 + ar)*K;
    const int br = tid >> 3, bcb = (tid & 7)*32;  // B: 32 rows x 256 cols, 4 cp16/thread

    float acc[4][8][4];
    #pragma unroll
    for (int a=0;a<4;a++)
        #pragma unroll
        for (int b=0;b<8;b++)
            #pragma unroll
            for (int c=0;c<4;c++) acc[a][b][c]=0.f;

    const int NIT = K >> 5;
    auto issue = [&](int it, int buf){
        int k0 = it << 5;
        __half* Ab = As + buf*128*ASTR;
        __half* Bb = Bs + buf*32*BSTR;
        if (azero){
            *(uint4*)(&Ab[ar*ASTR + ac])     = make_uint4(0,0,0,0);
            *(uint4*)(&Ab[ar*ASTR + ac + 8]) = make_uint4(0,0,0,0);
        } else {
            cp16(sptr(&Ab[ar*ASTR + ac]),     A + arow + k0 + ac);
            cp16(sptr(&Ab[ar*ASTR + ac + 8]), A + arow + k0 + ac + 8);
        }
        #pragma unroll
        for (int j = 0; j < 4; j++)
            cp16(sptr(&Bb[br*BSTR + bcb + j*8]), Bp + (long)(k0 + br)*N + col0 + bcb + j*8);
    };

    issue(0,0); cpcommit();
    issue(1,1); cpcommit();
    int cur = 0;
    for (int it = 0; it < NIT; ++it){
        cpwait<1>(); __syncthreads();
        if (it+2 < NIT){ issue(it+2, (it+2)%3); cpcommit(); }
        __half* Ab = As + cur*128*ASTR;
        __half* Bb = Bs + cur*32*BSTR;
        #pragma unroll
        for (int ks = 0; ks < 2; ++ks){
            uint32_t af[4][4];
            #pragma unroll
            for (int mf = 0; mf < 4; ++mf)
                ldsm4(af[mf], sptr(&Ab[(wm*64 + mf*16 + (lane&15))*ASTR + ks*16 + (lane>>4)*8]));
            uint32_t bf[8][2];
            #pragma unroll
            for (int nf2 = 0; nf2 < 4; ++nf2){
                uint32_t r[4];
                ldsm4t(r, sptr(&Bb[(ks*16 + (lane&15))*BSTR + wn*64 + nf2*16 + (lane>>4)*8]));
                bf[nf2*2][0]=r[0]; bf[nf2*2][1]=r[1]; bf[nf2*2+1][0]=r[2]; bf[nf2*2+1][1]=r[3];
            }
            #pragma unroll
            for (int mf = 0; mf < 4; ++mf)
                #pragma unroll
                for (int nt = 0; nt < 8; ++nt)
                    mma16816(acc[mf][nt], af[mf], bf[nt]);
        }
        cur = (cur+1)%3;
    }

    #pragma unroll
    for (int mf = 0; mf < 4; ++mf){
        int rbase = row0 + wm*64 + mf*16 + (lane>>2);
        #pragma unroll
        for (int nt = 0; nt < 8; ++nt){
            int c = col0 + wn*64 + nt*8 + (lane&3)*2;
            #pragma unroll
            for (int hh = 0; hh < 2; ++hh){
                int rr = rbase + hh*8;
                float v0 = acc[mf][nt][hh*2], v1 = acc[mf][nt][hh*2+1];
                if (EPI == 0){
                    float2 w2; w2.x = v0; w2.y = v1;
                    *(float2*)((float*)C + (long)rr*N + c) = w2;
                } else if (EPI == 1){
                    float2 rr2 = *(const float2*)(C2 + (long)rr*N + c);
                    float2 w2; w2.x = v0 + rr2.x; w2.y = v1 + rr2.y;
                    *(float2*)((float*)C + (long)rr*N + c) = w2;
                } else if (EPI == 3){
                    float sv = v0 / (1.f + __expf(-v0)) * v1;
                    ((__half*)C)[(long)rr*(N>>1) + (c>>1)] = __float2half(sv);
                } else { // EPI == 4: rope + split to q|k|v
                    __half* base = (__half*)C;
                    int cc_ = c;
                    if (c >= 2048){ base += 2l*NTOK*D_; cc_ = c - 2048; }
                    else if (c >= 1024){ base += (long)NTOK*D_; cc_ = c - 1024; }
                    if (c < 2048){
                        int s = rr & (S_-1);
                        int fi = (cc_ & 63) >> 1;
                        float co = fcp[s*32+fi], sn = fsp[s*32+fi];
                        *(__half2*)(base + (long)rr*D_ + cc_) =
                            __floats2half2_rn(v0*co - v1*sn, v0*sn + v1*co);
                    } else {
                        *(__half2*)(base + (long)rr*D_ + cc_) = __floats2half2_rn(v0, v1);
                    }
                }
            }
        }
    }
}

// ---------------- flash attention fp16 (FA2-style), 64 q-rows / block --------
__global__ __launch_bounds__(128) void flash_h_k(const __half* __restrict__ qh, const __half* __restrict__ kh,
                                                 const __half* __restrict__ vh, __half* __restrict__ o){
    __shared__ __half Qs[64*72];
    __shared__ __half Ks[2][64*72];
    __shared__ __half Vs[2][64*72];
    const int tid = threadIdx.x, lane = tid & 31, w = tid >> 5;
    const int bh = blockIdx.y, b = bh >> 4, h = bh & 15;
    const int q0 = blockIdx.x*64;
    const int lrow = tid >> 1, lc0 = (tid & 1)*4;

    {
        const __half* qb = qh + ((long)b*S_ + q0 + lrow)*D_ + h*64;
        #pragma unroll
        for (int c = 0; c < 4; c++)
            cp16(sptr(&Qs[lrow*72 + (lc0 + c)*8]), qb + (lc0 + c)*8);
        cpcommit();
    }
    auto issue_kv = [&](int kt, int buf){
        const __half* kb = kh + ((long)b*S_ + kt + lrow)*D_ + h*64;
        const __half* vb = vh + ((long)b*S_ + kt + lrow)*D_ + h*64;
        #pragma unroll
        for (int c = 0; c < 4; c++){
            cp16(sptr(&Ks[buf][lrow*72 + (lc0 + c)*8]), kb + (lc0 + c)*8);
            cp16(sptr(&Vs[buf][lrow*72 + (lc0 + c)*8]), vb + (lc0 + c)*8);
        }
    };
    issue_kv(0, 0); cpcommit();

    cpwait<1>(); __syncthreads();
    uint32_t aQ[4][4];
    #pragma unroll
    for (int ks = 0; ks < 4; ks++)
        ldsm4(aQ[ks], sptr(&Qs[(w*16 + (lane&15))*72 + ks*16 + (lane>>4)*8]));

    float oa[8][4];
    #pragma unroll
    for (int i = 0; i < 8; i++){ oa[i][0]=0.f; oa[i][1]=0.f; oa[i][2]=0.f; oa[i][3]=0.f; }
    float m0 = -1e30f, m1 = -1e30f, l0 = 0.f, l1 = 0.f;

    const int NKT = S_/64;
    for (int kti = 0; kti < NKT; ++kti){
        int cur = kti & 1;
        cpwait<0>(); __syncthreads();
        if (kti+1 < NKT){ issue_kv((kti+1)*64, cur^1); cpcommit(); }

        float sa[8][4];
        #pragma unroll
        for (int i = 0; i < 8; i++){ sa[i][0]=0.f; sa[i][1]=0.f; sa[i][2]=0.f; sa[i][3]=0.f; }
        #pragma unroll
        for (int ks = 0; ks < 4; ++ks){
            #pragma unroll
            for (int nf2 = 0; nf2 < 4; ++nf2){
                uint32_t r[4];
                ldsm4(r, sptr(&Ks[cur][(nf2*16 + (lane&15))*72 + ks*16 + (lane>>4)*8]));
                uint32_t blo[2] = {r[0], r[2]}, bhi[2] = {r[1], r[3]};
                mma16816(sa[nf2*2],   aQ[ks], blo);
                mma16816(sa[nf2*2+1], aQ[ks], bhi);
            }
        }
        float cm0 = -1e30f, cm1 = -1e30f;
        #pragma unroll
        for (int nt = 0; nt < 8; ++nt){
            sa[nt][0]*=0.125f; sa[nt][1]*=0.125f; sa[nt][2]*=0.125f; sa[nt][3]*=0.125f;
            cm0 = fmaxf(cm0, fmaxf(sa[nt][0], sa[nt][1]));
            cm1 = fmaxf(cm1, fmaxf(sa[nt][2], sa[nt][3]));
        }
        cm0 = fmaxf(cm0, __shfl_xor_sync(0xffffffffu, cm0, 1));
        cm0 = fmaxf(cm0, __shfl_xor_sync(0xffffffffu, cm0, 2));
        cm1 = fmaxf(cm1, __shfl_xor_sync(0xffffffffu, cm1, 1));
        cm1 = fmaxf(cm1, __shfl_xor_sync(0xffffffffu, cm1, 2));
        float nm0 = fmaxf(m0, cm0), nm1 = fmaxf(m1, cm1);
        float a0 = __expf(m0 - nm0), a1 = __expf(m1 - nm1);
        float rs0 = 0.f, rs1 = 0.f;
        #pragma unroll
        for (int nt = 0; nt < 8; ++nt){
            sa[nt][0] = __expf(sa[nt][0] - nm0); rs0 += sa[nt][0];
            sa[nt][1] = __expf(sa[nt][1] - nm0); rs0 += sa[nt][1];
            sa[nt][2] = __expf(sa[nt][2] - nm1); rs1 += sa[nt][2];
            sa[nt][3] = __expf(sa[nt][3] - nm1); rs1 += sa[nt][3];
        }
        rs0 += __shfl_xor_sync(0xffffffffu, rs0, 1);
        rs0 += __shfl_xor_sync(0xffffffffu, rs0, 2);
        rs1 += __shfl_xor_sync(0xffffffffu, rs1, 1);
        rs1 += __shfl_xor_sync(0xffffffffu, rs1, 2);
        l0 = l0*a0 + rs0; l1 = l1*a1 + rs1; m0 = nm0; m1 = nm1;
        #pragma unroll
        for (int nt = 0; nt < 8; ++nt){ oa[nt][0]*=a0; oa[nt][1]*=a0; oa[nt][2]*=a1; oa[nt][3]*=a1; }
        uint32_t pa[4][4];
        #pragma unroll
        for (int kf = 0; kf < 4; ++kf){
            pa[kf][0] = packh2(sa[2*kf][0],   sa[2*kf][1]);
            pa[kf][1] = packh2(sa[2*kf][2],   sa[2*kf][3]);
            pa[kf][2] = packh2(sa[2*kf+1][0], sa[2*kf+1][1]);
            pa[kf][3] = packh2(sa[2*kf+1][2], sa[2*kf+1][3]);
        }
        #pragma unroll
        for (int kf = 0; kf < 4; ++kf){
            #pragma unroll
            for (int nf2 = 0; nf2 < 4; ++nf2){
                uint32_t r[4];
                ldsm4t(r, sptr(&Vs[cur][(kf*16 + (lane&15))*72 + nf2*16 + (lane>>4)*8]));
                uint32_t blo[2] = {r[0], r[1]}, bhi[2] = {r[2], r[3]};
                mma16816(oa[nf2*2],   pa[kf], blo);
                mma16816(oa[nf2*2+1], pa[kf], bhi);
            }
        }
    }

    float il0 = 1.f / l0, il1 = 1.f / l1;
    int rlo = q0 + w*16 + (lane>>2);
    #pragma unroll
    for (int nt = 0; nt < 8; ++nt){
        int c = h*64 + nt*8 + (lane&3)*2;
        *(__half2*)(o + ((long)b*S_ + rlo)*D_ + c)     = __floats2half2_rn(oa[nt][0]*il0, oa[nt][1]*il0);
        *(__half2*)(o + ((long)b*S_ + rlo + 8)*D_ + c) = __floats2half2_rn(oa[nt][2]*il1, oa[nt][3]*il1);
    }
}

// ---------------- MoE routing ----------------
__global__ __launch_bounds__(256) void moe_init_k(){
    int i = blockIdx.x*256 + threadIdx.x;
    if (i < MROWS) g_gather[i] = -1;
    if (i < E_){ g_counts[i] = 0; g_cursor[i] = 0; }
}

__global__ __launch_bounds__(256) void gate_k(const float* __restrict__ xf, const float* __restrict__ gw){
    int n = blockIdx.x;
    int tid = threadIdx.x, w = tid >> 5, lane = tid & 31;
    const float* xr = xf + (long)n * D_;
    const float* gr = gw + (long)w * D_;
    float s = 0.f;
    for (int d = lane; d < D_; d += 32) s += xr[d] * gr[d];
    #pragma unroll
    for (int o = 16; o; o >>= 1) s += __shfl_xor_sync(0xffffffffu, s, o);
    __shared__ float sc[E_];
    if (lane == 0) sc[w] = s;
    __syncthreads();
    if (tid == 0){
        float mx = sc[0];
        for (int e = 1; e < E_; e++) mx = fmaxf(mx, sc[e]);
        float p[E_]; float sum = 0.f;
        for (int e = 0; e < E_; e++){ p[e] = expf(sc[e] - mx); sum += p[e]; }
        float inv = 1.f / sum;
        for (int e = 0; e < E_; e++) p[e] *= inv;
        int e0 = 0;
        for (int e = 1; e < E_; e++) if (p[e] > p[e0]) e0 = e;
        int e1 = (e0 == 0) ? 1 : 0;
        for (int e = 0; e < E_; e++){ if (e == e0) continue; if (p[e] > p[e1]) e1 = e; }
        float v0 = p[e0], v1 = p[e1];
        float wi = 1.f / (v0 + v1 + 1e-9f);
        g_tokE[2*n] = e0; g_tokE[2*n+1] = e1;
        g_tokW[2*n] = v0*wi; g_tokW[2*n+1] = v1*wi;
        atomicAdd(&g_counts[e0], 1);
        atomicAdd(&g_counts[e1], 1);
    }
}

__global__ void offsets_k(){
    if (threadIdx.x == 0){
        int acc = 0;
        for (int e = 0; e < E_; e++){ g_padbase[e] = acc; acc += ((g_counts[e] + 127) >> 7) << 7; }
        g_padbase[E_] = acc;
    }
    __syncthreads();
    int t = threadIdx.x;
    if (t < NTILES){
        int start = t*128, te = 0;
        if (start < g_padbase[E_]){
            for (int e = 0; e < E_; e++)
                if (start >= g_padbase[e] && start < g_padbase[e+1]) te = e;
        }
        g_tileE[t] = te;
    }
}

__global__ __launch_bounds__(256) void scatter_k(){
    int n = blockIdx.x*256 + threadIdx.x;
    if (n >= NTOK) return;
    #pragma unroll
    for (int kk = 0; kk < 2; kk++){
        int e = g_tokE[2*n + kk];
        int slot = atomicAdd(&g_cursor[e], 1);
        int pos = g_padbase[e] + slot;
        g_gather[pos] = n;
        g_tokPos[2*n + kk] = pos;
    }
}

__global__ __launch_bounds__(256) void combine_k(float* __restrict__ out){
    int i = blockIdx.x*256 + threadIdx.x;
    int n = i >> 10, d = i & 1023;
    float v = g_h[i] + g_sh[i];
    v += g_tokW[2*n]   * g_eo[(long)g_tokPos[2*n]  * D_ + d];
    v += g_tokW[2*n+1] * g_eo[(long)g_tokPos[2*n+1]* D_ + d];
    out[i] = v;
}

// ---------------- host orchestration ----------------
extern "C" void kernel_launch(void* const* d_in, const int* in_sizes, int n_in,
                              void* d_out, int out_size) {
    const float* x   = (const float*)d_in[0];
    const float* fc  = (const float*)d_in[1];
    const float* fs  = (const float*)d_in[2];
    const float* anw = (const float*)d_in[3];
    const float* fnw = (const float*)d_in[4];
    const float* wq  = (const float*)d_in[5];
    const float* wk  = (const float*)d_in[6];
    const float* wv  = (const float*)d_in[7];
    const float* wo  = (const float*)d_in[8];
    const float* gw  = (const float*)d_in[9];
    const float* ew1 = (const float*)d_in[10];
    const float* ew2 = (const float*)d_in[11];
    const float* ew3 = (const float*)d_in[12];
    const float* sw1 = (const float*)d_in[13];
    const float* sw2 = (const float*)d_in[14];
    const float* sw3 = (const float*)d_in[15];
    float* out = (float*)d_out;

    float *h,*xf,*sh,*eo;
    __half *qkvs,*xnh,*atth,*xfh,*th,*h1h;
    __half *wqkvh,*woh,*w13h,*sw2h,*ew13h,*ew2h;
    int *gath,*tileE;
    cudaGetSymbolAddress((void**)&h,    g_h);
    cudaGetSymbolAddress((void**)&xf,   g_xf);
    cudaGetSymbolAddress((void**)&sh,   g_sh);
    cudaGetSymbolAddress((void**)&eo,   g_eo);
    cudaGetSymbolAddress((void**)&qkvs, g_qkvs);
    cudaGetSymbolAddress((void**)&xnh,  g_xnh);
    cudaGetSymbolAddress((void**)&atth, g_atth);
    cudaGetSymbolAddress((void**)&xfh,  g_xfh);
    cudaGetSymbolAddress((void**)&th,   g_th);
    cudaGetSymbolAddress((void**)&h1h,  g_h1h);
    cudaGetSymbolAddress((void**)&wqkvh,g_wqkvh);
    cudaGetSymbolAddress((void**)&woh,  g_woh);
    cudaGetSymbolAddress((void**)&w13h, g_w13h);
    cudaGetSymbolAddress((void**)&sw2h, g_sw2h);
    cudaGetSymbolAddress((void**)&ew13h,g_ew13h);
    cudaGetSymbolAddress((void**)&ew2h, g_ew2h);
    cudaGetSymbolAddress((void**)&gath,  g_gather);
    cudaGetSymbolAddress((void**)&tileE, g_tileE);

    __half* qh = qkvs;
    __half* kh = qkvs + (long)NTOK*D_;
    __half* vh = qkvs + 2l*NTOK*D_;

    cudaFuncSetAttribute(hgemm_k<float,0>,  cudaFuncAttributeMaxDynamicSharedMemorySize, GEMM_SMEM);
    cudaFuncSetAttribute(hgemm_k<float,1>,  cudaFuncAttributeMaxDynamicSharedMemorySize, GEMM_SMEM);
    cudaFuncSetAttribute(hgemm_k<__half,3>, cudaFuncAttributeMaxDynamicSharedMemorySize, GEMM_SMEM);
    cudaFuncSetAttribute(hgemm_k<__half,4>, cudaFuncAttributeMaxDynamicSharedMemorySize, GEMM_SMEM);

    // 0: merged weight conversion
    cvtall_k<<<(22*M1Q)/256, 256>>>(
        (const float4*)wq, (const float4*)wk, (const float4*)wv,
        (const float4*)wo, (const float4*)sw1, (const float4*)sw2, (const float4*)sw3,
        (const float4*)ew1, (const float4*)ew2, (const float4*)ew3);
    // 1: moe init
    moe_init_k<<<(MROWS + 255)/256, 256>>>();
    // 2: rmsnorm -> xnh
    rmsnorm_k<<<NTOK, 256>>>(x, anw, nullptr, xnh);
    // 3: QKV gemm + fused rope (N=3072, 12 col tiles)
    hgemm_k<__half,4><<<dim3(12,32), 256, GEMM_SMEM>>>(xnh, wqkvh, qkvs, nullptr, 1024, 3072,
                                                       nullptr, nullptr, 0, fc, fs);
    // 4: flash attention
    flash_h_k<<<dim3(S_/64, B_*H_), 128>>>(qh, kh, vh, atth);
    // 5: wo projection + residual  (<- ncu -s 5)
    hgemm_k<float,1><<<dim3(4,32), 256, GEMM_SMEM>>>(atth, woh, h, x, 1024, 1024,
                                                     nullptr, nullptr, 0, nullptr, nullptr);
    // 6: rmsnorm -> xf, xfh
    rmsnorm_k<<<NTOK, 256>>>(h, fnw, xf, xfh);
    // 7: fused shared FFN up (N=2048, 8 col tiles)
    hgemm_k<__half,3><<<dim3(8,32), 256, GEMM_SMEM>>>(xfh, w13h, th, nullptr, 1024, 2048,
                                                      nullptr, nullptr, 0, nullptr, nullptr);
    // 8: shared FFN down
    hgemm_k<float,0><<<dim3(4,32), 256, GEMM_SMEM>>>(th, sw2h, sh, nullptr, 1024, 1024,
                                                     nullptr, nullptr, 0, nullptr, nullptr);
    // 9-11: routing
    gate_k<<<NTOK, 256>>>(xf, gw);
    offsets_k<<<1, 128>>>();
    scatter_k<<<NTOK/256, 256>>>();
    // 12: fused MoE up (gathered)
    hgemm_k<__half,3><<<dim3(8,NTILES), 256, GEMM_SMEM>>>(xfh, ew13h, h1h, nullptr, 1024, 2048,
                                                          gath, tileE, 1024l*2048, nullptr, nullptr);
    // 13: MoE down
    hgemm_k<float,0><<<dim3(4,NTILES), 256, GEMM_SMEM>>>(h1h, ew2h, eo, nullptr, 1024, 1024,
                                                         nullptr, tileE, 1024l*1024, nullptr, nullptr);
    // 14: combine
    combine_k<<<(NTOK*D_)/256, 256>>>(out);
}

// round 12
// speedup vs baseline: 1.1528x; 1.1495x over previous
#include <cuda_runtime.h>
#include <cuda_fp16.h>
#include <cstdint>
#include <math.h>

#define B_    2
#define S_    2048
#define D_    1024
#define H_    16
#define NTOK  4096
#define E_    8
#define MROWS 9216
#define AROWS (MROWS + NTOK)   // routed (padded) + shared identity rows = 13312
#define NTILES 72              // routed tiles
#define NT_ALL 104             // + 32 shared tiles
#define M1Q   262144           // (1024*1024)/4 float4s per 1M-element matrix

#define ASTR 40
#define BSTR 136
#define GEMM_SMEM (3*(128*ASTR + 32*BSTR)*2)   // 56832 bytes

// ---------------- device scratch ----------------
__device__ float g_h  [NTOK*D_];
__device__ float g_xf [NTOK*D_];
__device__ float g_eo [AROWS*D_];

__device__ __half g_qkvs[3*NTOK*D_];   // q | k | v (post-rope)
__device__ __half g_xnh [NTOK*D_];
__device__ __half g_atth[NTOK*D_];
__device__ __half g_xfh [NTOK*D_];
__device__ __half g_h1h [AROWS*D_];

__device__ __half g_wqkvh[D_*3072];
__device__ __half g_woh  [D_*D_];
__device__ __half g_ew13h[(E_+1)*D_*2048];   // experts 0-7 + shared(8), interleaved w1/w3
__device__ __half g_ew2h [(E_+1)*D_*D_];     // experts 0-7 + shared(8)

__device__ int   g_counts [E_];
__device__ int   g_cursor [E_];
__device__ int   g_padbase[E_+1];
__device__ int   g_tileE  [NT_ALL];
__device__ int   g_gather [AROWS];
__device__ int   g_tokE   [NTOK*2];
__device__ float g_tokW   [NTOK*2];
__device__ int   g_tokPos [NTOK*2];

// ---------------- ptx helpers ----------------
__device__ __forceinline__ uint32_t sptr(const void* p){ return (uint32_t)__cvta_generic_to_shared(p); }
__device__ __forceinline__ void ldsm4(uint32_t* r, uint32_t a){
    asm volatile("ldmatrix.sync.aligned.m8n8.x4.shared.b16 {%0,%1,%2,%3},[%4];"
        :"=r"(r[0]),"=r"(r[1]),"=r"(r[2]),"=r"(r[3]):"r"(a));
}
__device__ __forceinline__ void ldsm4t(uint32_t* r, uint32_t a){
    asm volatile("ldmatrix.sync.aligned.m8n8.x4.trans.shared.b16 {%0,%1,%2,%3},[%4];"
        :"=r"(r[0]),"=r"(r[1]),"=r"(r[2]),"=r"(r[3]):"r"(a));
}
__device__ __forceinline__ void mma16816(float* c, const uint32_t* a, const uint32_t* b){
    asm volatile("mma.sync.aligned.m16n8k16.row.col.f32.f16.f16.f32 "
        "{%0,%1,%2,%3},{%4,%5,%6,%7},{%8,%9},{%0,%1,%2,%3};"
        :"+f"(c[0]),"+f"(c[1]),"+f"(c[2]),"+f"(c[3])
        :"r"(a[0]),"r"(a[1]),"r"(a[2]),"r"(a[3]),"r"(b[0]),"r"(b[1]));
}
__device__ __forceinline__ void cp16(uint32_t d, const void* s){
    asm volatile("cp.async.cg.shared.global [%0],[%1],16;"::"r"(d),"l"(s));
}
__device__ __forceinline__ void cpcommit(){ asm volatile("cp.async.commit_group;"); }
template<int N> __device__ __forceinline__ void cpwait(){ asm volatile("cp.async.wait_group %0;"::"n"(N)); }
__device__ __forceinline__ uint32_t packh2(float a, float b){
    __half2 h = __floats2half2_rn(a,b); return *(uint32_t*)&h;
}

// ---------------- merged weight conversion (fp32 -> fp16, with layout fusion) ----
// regions (float4 index):
// [0,Q): wo | [Q,2Q): sw2 -> ew2h[8] | [2Q,3Q): sw1+sw3 -> ew13h[8] interleaved
// [3Q,11Q): ew2 experts 0-7 | [11Q,19Q): ew1+ew3 -> ew13h 0-7 | [19Q,22Q): wq,wk,wv
__global__ __launch_bounds__(256) void cvtall_k(
    const float4* __restrict__ wq, const float4* __restrict__ wk, const float4* __restrict__ wv,
    const float4* __restrict__ wo, const float4* __restrict__ sw1,
    const float4* __restrict__ sw2, const float4* __restrict__ sw3,
    const float4* __restrict__ ew1, const float4* __restrict__ ew2, const float4* __restrict__ ew3)
{
    int i = blockIdx.x*256 + threadIdx.x;
    if (i < M1Q){
        float4 v = wo[i];
        uint2 p; p.x = packh2(v.x,v.y); p.y = packh2(v.z,v.w);
        *(uint2*)(g_woh + (long)i*4) = p;
    } else if (i < 2*M1Q){
        int t = i - M1Q;
        float4 v = sw2[t];
        uint2 p; p.x = packh2(v.x,v.y); p.y = packh2(v.z,v.w);
        *(uint2*)(g_ew2h + 8l*1048576 + (long)t*4) = p;
    } else if (i < 3*M1Q){
        int t = i - 2*M1Q;
        long e4 = (long)t*4;
        float4 a = sw1[t], b = sw3[t];
        uint4 p; p.x = packh2(a.x,b.x); p.y = packh2(a.y,b.y);
        p.z = packh2(a.z,b.z); p.w = packh2(a.w,b.w);
        *(uint4*)(g_ew13h + 8l*2097152 + (e4>>10)*2048 + 2*(e4&1023)) = p;
    } else if (i < 11*M1Q){
        int t = i - 3*M1Q;
        float4 v = ew2[t];
        uint2 p; p.x = packh2(v.x,v.y); p.y = packh2(v.z,v.w);
        *(uint2*)(g_ew2h + (long)t*4) = p;
    } else if (i < 19*M1Q){
        int t = i - 11*M1Q;
        long e4 = (long)t*4;
        long ex = e4 >> 20;
        long rem = e4 & 1048575;
        float4 a = ew1[t], b = ew3[t];
        uint4 p; p.x = packh2(a.x,b.x); p.y = packh2(a.y,b.y);
        p.z = packh2(a.z,b.z); p.w = packh2(a.w,b.w);
        *(uint4*)(g_ew13h + ex*2097152 + (rem>>10)*2048 + 2*(rem&1023)) = p;
    } else {
        int j = i - 19*M1Q;
        int m = j >> 18, t = j & (M1Q-1);
        const float4* s = (m==0)? wq : (m==1)? wk : wv;
        float4 v = s[t];
        long e = (long)t*4;
        uint2 p; p.x = packh2(v.x,v.y); p.y = packh2(v.z,v.w);
        *(uint2*)(g_wqkvh + (e>>10)*3072 + m*1024 + (e&1023)) = p;
    }
}

// ---------------- rmsnorm ----------------
__global__ __launch_bounds__(256) void rmsnorm_k(const float* __restrict__ x, const float* __restrict__ w,
                                                 float* __restrict__ yf, __half* __restrict__ yh){
    int n = blockIdx.x;
    const float* xr = x + (long)n * D_;
    float v[4]; float ss = 0.f;
    #pragma unroll
    for (int u = 0; u < 4; u++){ v[u] = xr[threadIdx.x + u*256]; ss += v[u]*v[u]; }
    __shared__ float red[256];
    red[threadIdx.x] = ss; __syncthreads();
    for (int s = 128; s > 0; s >>= 1){
        if (threadIdx.x < s) red[threadIdx.x] += red[threadIdx.x + s];
        __syncthreads();
    }
    float r = rsqrtf(red[0] / (float)D_ + 1e-6f);
    #pragma unroll
    for (int u = 0; u < 4; u++){
        int c = threadIdx.x + u*256;
        float val = v[u]*r*w[c];
        yh[(long)n*D_ + c] = __float2half(val);
        if (yf) yf[(long)n*D_ + c] = val;
    }
}

// ---------------- HGEMM 128x128x32, 3-stage cp.async, mma.sync (R7 config) ---
// EPI: 0 C=acc(f32) ; 1 C=acc+C2 (f32) ; 3 fused silu-mul (half, N/2 wide) ;
//      4 fused rope qkv epilogue
template<typename OutT, int EPI>
__global__ __launch_bounds__(256) void hgemm_k(
    const __half* __restrict__ A, const __half* __restrict__ Bw,
    OutT* __restrict__ C, const float* __restrict__ C2,
    int K, int N,
    const int* __restrict__ gatherIdx, const int* __restrict__ tileExpert, long estride,
    const int* __restrict__ skipIdx,
    const float* __restrict__ fcp, const float* __restrict__ fsp)
{
    const int row0 = blockIdx.y*128, col0 = blockIdx.x*128;
    if (skipIdx && skipIdx[row0] < 0) return;   // fully-padded tile, output unused

    extern __shared__ __half smem[];
    __half* As = smem;                    // 3 stages of 128*ASTR
    __half* Bs = smem + 3*128*ASTR;       // 3 stages of 32*BSTR
    const int tid = threadIdx.x, lane = tid & 31, wid = tid >> 5;
    const int wm = wid & 1, wn = wid >> 1;
    const __half* Bp = Bw + (tileExpert ? (long)tileExpert[blockIdx.y]*estride : 0);

    const int ar = tid >> 1, ac = tid & 1;
    long arow = 0; bool azero = false;
    if (gatherIdx){ int g = gatherIdx[row0 + ar]; if (g < 0) azero = true; else arow = (long)g*K; }
    else arow = (long)(row0 + ar)*K;
    const int br = tid >> 4, bc = tid & 15;

    float acc[4][4][4];
    #pragma unroll
    for (int a=0;a<4;a++)
        #pragma unroll
        for (int b=0;b<4;b++)
            #pragma unroll
            for (int c=0;c<4;c++) acc[a][b][c]=0.f;

    const int NIT = K >> 5;
    auto issue = [&](int it, int buf){
        int k0 = it << 5;
        __half* Ab = As + buf*128*ASTR;
        __half* Bb = Bs + buf*32*BSTR;
        #pragma unroll
        for (int u = 0; u < 2; u++){
            int c = ac + u*2;
            if (azero) *(uint4*)(&Ab[ar*ASTR + c*8]) = make_uint4(0,0,0,0);
            else cp16(sptr(&Ab[ar*ASTR + c*8]), A + arow + k0 + c*8);
        }
        #pragma unroll
        for (int u = 0; u < 2; u++){
            int r = br + u*16;
            cp16(sptr(&Bb[r*BSTR + bc*8]), Bp + (long)(k0 + r)*N + col0 + bc*8);
        }
    };

    issue(0,0); cpcommit();
    issue(1,1); cpcommit();
    int cur = 0;
    for (int it = 0; it < NIT; ++it){
        cpwait<1>(); __syncthreads();
        if (it+2 < NIT){ issue(it+2, (it+2)%3); cpcommit(); }
        __half* Ab = As + cur*128*ASTR;
        __half* Bb = Bs + cur*32*BSTR;
        #pragma unroll
        for (int ks = 0; ks < 2; ++ks){
            uint32_t af[4][4];
            #pragma unroll
            for (int mf = 0; mf < 4; ++mf)
                ldsm4(af[mf], sptr(&Ab[(wm*64 + mf*16 + (lane&15))*ASTR + ks*16 + (lane>>4)*8]));
            uint32_t bf[4][2];
            #pragma unroll
            for (int nf2 = 0; nf2 < 2; ++nf2){
                uint32_t r[4];
                ldsm4t(r, sptr(&Bb[(ks*16 + (lane&15))*BSTR + wn*32 + nf2*16 + (lane>>4)*8]));
                bf[nf2*2][0]=r[0]; bf[nf2*2][1]=r[1]; bf[nf2*2+1][0]=r[2]; bf[nf2*2+1][1]=r[3];
            }
            #pragma unroll
            for (int mf = 0; mf < 4; ++mf)
                #pragma unroll
                for (int nt = 0; nt < 4; ++nt)
                    mma16816(acc[mf][nt], af[mf], bf[nt]);
        }
        cur = (cur+1)%3;
    }

    #pragma unroll
    for (int mf = 0; mf < 4; ++mf){
        int rbase = row0 + wm*64 + mf*16 + (lane>>2);
        #pragma unroll
        for (int nt = 0; nt < 4; ++nt){
            int c = col0 + wn*32 + nt*8 + (lane&3)*2;
            #pragma unroll
            for (int hh = 0; hh < 2; ++hh){
                int rr = rbase + hh*8;
                float v0 = acc[mf][nt][hh*2], v1 = acc[mf][nt][hh*2+1];
                if (EPI == 0){
                    float2 w2; w2.x = v0; w2.y = v1;
                    *(float2*)((float*)C + (long)rr*N + c) = w2;
                } else if (EPI == 1){
                    float2 rr2 = *(const float2*)(C2 + (long)rr*N + c);
                    float2 w2; w2.x = v0 + rr2.x; w2.y = v1 + rr2.y;
                    *(float2*)((float*)C + (long)rr*N + c) = w2;
                } else if (EPI == 3){
                    float sv = v0 / (1.f + __expf(-v0)) * v1;
                    ((__half*)C)[(long)rr*(N>>1) + (c>>1)] = __float2half(sv);
                } else { // EPI == 4: rope + split to q|k|v
                    __half* base = (__half*)C;
                    int cc_ = c;
                    if (c >= 2048){ base += 2l*NTOK*D_; cc_ = c - 2048; }
                    else if (c >= 1024){ base += (long)NTOK*D_; cc_ = c - 1024; }
                    if (c < 2048){
                        int s = rr & (S_-1);
                        int fi = (cc_ & 63) >> 1;
                        float co = fcp[s*32+fi], sn = fsp[s*32+fi];
                        *(__half2*)(base + (long)rr*D_ + cc_) =
                            __floats2half2_rn(v0*co - v1*sn, v0*sn + v1*co);
                    } else {
                        *(__half2*)(base + (long)rr*D_ + cc_) = __floats2half2_rn(v0, v1);
                    }
                }
            }
        }
    }
}

// ---------------- flash attention fp16 (FA2-style), 64 q-rows / block --------
__global__ __launch_bounds__(128) void flash_h_k(const __half* __restrict__ qh, const __half* __restrict__ kh,
                                                 const __half* __restrict__ vh, __half* __restrict__ o){
    __shared__ __half Qs[64*72];
    __shared__ __half Ks[2][64*72];
    __shared__ __half Vs[2][64*72];
    const int tid = threadIdx.x, lane = tid & 31, w = tid >> 5;
    const int bh = blockIdx.y, b = bh >> 4, h = bh & 15;
    const int q0 = blockIdx.x*64;
    const int lrow = tid >> 1, lc0 = (tid & 1)*4;

    {
        const __half* qb = qh + ((long)b*S_ + q0 + lrow)*D_ + h*64;
        #pragma unroll
        for (int c = 0; c < 4; c++)
            cp16(sptr(&Qs[lrow*72 + (lc0 + c)*8]), qb + (lc0 + c)*8);
        cpcommit();
    }
    auto issue_kv = [&](int kt, int buf){
        const __half* kb = kh + ((long)b*S_ + kt + lrow)*D_ + h*64;
        const __half* vb = vh + ((long)b*S_ + kt + lrow)*D_ + h*64;
        #pragma unroll
        for (int c = 0; c < 4; c++){
            cp16(sptr(&Ks[buf][lrow*72 + (lc0 + c)*8]), kb + (lc0 + c)*8);
            cp16(sptr(&Vs[buf][lrow*72 + (lc0 + c)*8]), vb + (lc0 + c)*8);
        }
    };
    issue_kv(0, 0); cpcommit();

    cpwait<1>(); __syncthreads();
    uint32_t aQ[4][4];
    #pragma unroll
    for (int ks = 0; ks < 4; ks++)
        ldsm4(aQ[ks], sptr(&Qs[(w*16 + (lane&15))*72 + ks*16 + (lane>>4)*8]));

    float oa[8][4];
    #pragma unroll
    for (int i = 0; i < 8; i++){ oa[i][0]=0.f; oa[i][1]=0.f; oa[i][2]=0.f; oa[i][3]=0.f; }
    float m0 = -1e30f, m1 = -1e30f, l0 = 0.f, l1 = 0.f;

    const int NKT = S_/64;
    for (int kti = 0; kti < NKT; ++kti){
        int cur = kti & 1;
        cpwait<0>(); __syncthreads();
        if (kti+1 < NKT){ issue_kv((kti+1)*64, cur^1); cpcommit(); }

        float sa[8][4];
        #pragma unroll
        for (int i = 0; i < 8; i++){ sa[i][0]=0.f; sa[i][1]=0.f; sa[i][2]=0.f; sa[i][3]=0.f; }
        #pragma unroll
        for (int ks = 0; ks < 4; ++ks){
            #pragma unroll
            for (int nf2 = 0; nf2 < 4; ++nf2){
                uint32_t r[4];
                ldsm4(r, sptr(&Ks[cur][(nf2*16 + (lane&15))*72 + ks*16 + (lane>>4)*8]));
                uint32_t blo[2] = {r[0], r[2]}, bhi[2] = {r[1], r[3]};
                mma16816(sa[nf2*2],   aQ[ks], blo);
                mma16816(sa[nf2*2+1], aQ[ks], bhi);
            }
        }
        float cm0 = -1e30f, cm1 = -1e30f;
        #pragma unroll
        for (int nt = 0; nt < 8; ++nt){
            sa[nt][0]*=0.125f; sa[nt][1]*=0.125f; sa[nt][2]*=0.125f; sa[nt][3]*=0.125f;
            cm0 = fmaxf(cm0, fmaxf(sa[nt][0], sa[nt][1]));
            cm1 = fmaxf(cm1, fmaxf(sa[nt][2], sa[nt][3]));
        }
        cm0 = fmaxf(cm0, __shfl_xor_sync(0xffffffffu, cm0, 1));
        cm0 = fmaxf(cm0, __shfl_xor_sync(0xffffffffu, cm0, 2));
        cm1 = fmaxf(cm1, __shfl_xor_sync(0xffffffffu, cm1, 1));
        cm1 = fmaxf(cm1, __shfl_xor_sync(0xffffffffu, cm1, 2));
        float nm0 = fmaxf(m0, cm0), nm1 = fmaxf(m1, cm1);
        float a0 = __expf(m0 - nm0), a1 = __expf(m1 - nm1);
        float rs0 = 0.f, rs1 = 0.f;
        #pragma unroll
        for (int nt = 0; nt < 8; ++nt){
            sa[nt][0] = __expf(sa[nt][0] - nm0); rs0 += sa[nt][0];
            sa[nt][1] = __expf(sa[nt][1] - nm0); rs0 += sa[nt][1];
            sa[nt][2] = __expf(sa[nt][2] - nm1); rs1 += sa[nt][2];
            sa[nt][3] = __expf(sa[nt][3] - nm1); rs1 += sa[nt][3];
        }
        rs0 += __shfl_xor_sync(0xffffffffu, rs0, 1);
        rs0 += __shfl_xor_sync(0xffffffffu, rs0, 2);
        rs1 += __shfl_xor_sync(0xffffffffu, rs1, 1);
        rs1 += __shfl_xor_sync(0xffffffffu, rs1, 2);
        l0 = l0*a0 + rs0; l1 = l1*a1 + rs1; m0 = nm0; m1 = nm1;
        #pragma unroll
        for (int nt = 0; nt < 8; ++nt){ oa[nt][0]*=a0; oa[nt][1]*=a0; oa[nt][2]*=a1; oa[nt][3]*=a1; }
        uint32_t pa[4][4];
        #pragma unroll
        for (int kf = 0; kf < 4; ++kf){
            pa[kf][0] = packh2(sa[2*kf][0],   sa[2*kf][1]);
            pa[kf][1] = packh2(sa[2*kf][2],   sa[2*kf][3]);
            pa[kf][2] = packh2(sa[2*kf+1][0], sa[2*kf+1][1]);
            pa[kf][3] = packh2(sa[2*kf+1][2], sa[2*kf+1][3]);
        }
        #pragma unroll
        for (int kf = 0; kf < 4; ++kf){
            #pragma unroll
            for (int nf2 = 0; nf2 < 4; ++nf2){
                uint32_t r[4];
                ldsm4t(r, sptr(&Vs[cur][(kf*16 + (lane&15))*72 + nf2*16 + (lane>>4)*8]));
                uint32_t blo[2] = {r[0], r[1]}, bhi[2] = {r[2], r[3]};
                mma16816(oa[nf2*2],   pa[kf], blo);
                mma16816(oa[nf2*2+1], pa[kf], bhi);
            }
        }
    }

    float il0 = 1.f / l0, il1 = 1.f / l1;
    int rlo = q0 + w*16 + (lane>>2);
    #pragma unroll
    for (int nt = 0; nt < 8; ++nt){
        int c = h*64 + nt*8 + (lane&3)*2;
        *(__half2*)(o + ((long)b*S_ + rlo)*D_ + c)     = __floats2half2_rn(oa[nt][0]*il0, oa[nt][1]*il0);
        *(__half2*)(o + ((long)b*S_ + rlo + 8)*D_ + c) = __floats2half2_rn(oa[nt][2]*il1, oa[nt][3]*il1);
    }
}

// ---------------- MoE routing ----------------
__global__ __launch_bounds__(256) void moe_init_k(){
    int i = blockIdx.x*256 + threadIdx.x;
    if (i < MROWS) g_gather[i] = -1;
    else if (i < AROWS) g_gather[i] = i - MROWS;   // shared tiles: identity gather
    if (i < E_){ g_counts[i] = 0; g_cursor[i] = 0; }
}

__global__ __launch_bounds__(256) void gate_k(const float* __restrict__ xf, const float* __restrict__ gw){
    int n = blockIdx.x;
    int tid = threadIdx.x, w = tid >> 5, lane = tid & 31;
    const float* xr = xf + (long)n * D_;
    const float* gr = gw + (long)w * D_;
    float s = 0.f;
    for (int d = lane; d < D_; d += 32) s += xr[d] * gr[d];
    #pragma unroll
    for (int o = 16; o; o >>= 1) s += __shfl_xor_sync(0xffffffffu, s, o);
    __shared__ float sc[E_];
    if (lane == 0) sc[w] = s;
    __syncthreads();
    if (tid == 0){
        float mx = sc[0];
        for (int e = 1; e < E_; e++) mx = fmaxf(mx, sc[e]);
        float p[E_]; float sum = 0.f;
        for (int e = 0; e < E_; e++){ p[e] = expf(sc[e] - mx); sum += p[e]; }
        float inv = 1.f / sum;
        for (int e = 0; e < E_; e++) p[e] *= inv;
        int e0 = 0;
        for (int e = 1; e < E_; e++) if (p[e] > p[e0]) e0 = e;
        int e1 = (e0 == 0) ? 1 : 0;
        for (int e = 0; e < E_; e++){ if (e == e0) continue; if (p[e] > p[e1]) e1 = e; }
        float v0 = p[e0], v1 = p[e1];
        float wi = 1.f / (v0 + v1 + 1e-9f);
        g_tokE[2*n] = e0; g_tokE[2*n+1] = e1;
        g_tokW[2*n] = v0*wi; g_tokW[2*n+1] = v1*wi;
        atomicAdd(&g_counts[e0], 1);
        atomicAdd(&g_counts[e1], 1);
    }
}

__global__ void offsets_k(){
    if (threadIdx.x == 0){
        int acc = 0;
        for (int e = 0; e < E_; e++){ g_padbase[e] = acc; acc += ((g_counts[e] + 127) >> 7) << 7; }
        g_padbase[E_] = acc;
    }
    __syncthreads();
    int t = threadIdx.x;
    if (t < NT_ALL){
        if (t >= NTILES){ g_tileE[t] = E_; }     // shared expert
        else {
            int start = t*128, te = 0;
            if (start < g_padbase[E_]){
                for (int e = 0; e < E_; e++)
                    if (start >= g_padbase[e] && start < g_padbase[e+1]) te = e;
            }
            g_tileE[t] = te;
        }
    }
}

__global__ __launch_bounds__(256) void scatter_k(){
    int n = blockIdx.x*256 + threadIdx.x;
    if (n >= NTOK) return;
    #pragma unroll
    for (int kk = 0; kk < 2; kk++){
        int e = g_tokE[2*n + kk];
        int slot = atomicAdd(&g_cursor[e], 1);
        int pos = g_padbase[e] + slot;
        g_gather[pos] = n;
        g_tokPos[2*n + kk] = pos;
    }
}

__global__ __launch_bounds__(256) void combine_k(float* __restrict__ out){
    int i = blockIdx.x*256 + threadIdx.x;
    int n = i >> 10, d = i & 1023;
    float v = g_h[i] + g_eo[(long)(MROWS + n)*D_ + d];   // residual + shared FFN
    v += g_tokW[2*n]   * g_eo[(long)g_tokPos[2*n]  * D_ + d];
    v += g_tokW[2*n+1] * g_eo[(long)g_tokPos[2*n+1]* D_ + d];
    out[i] = v;
}

// ---------------- host orchestration ----------------
extern "C" void kernel_launch(void* const* d_in, const int* in_sizes, int n_in,
                              void* d_out, int out_size) {
    const float* x   = (const float*)d_in[0];
    const float* fc  = (const float*)d_in[1];
    const float* fs  = (const float*)d_in[2];
    const float* anw = (const float*)d_in[3];
    const float* fnw = (const float*)d_in[4];
    const float* wq  = (const float*)d_in[5];
    const float* wk  = (const float*)d_in[6];
    const float* wv  = (const float*)d_in[7];
    const float* wo  = (const float*)d_in[8];
    const float* gw  = (const float*)d_in[9];
    const float* ew1 = (const float*)d_in[10];
    const float* ew2 = (const float*)d_in[11];
    const float* ew3 = (const float*)d_in[12];
    const float* sw1 = (const float*)d_in[13];
    const float* sw2 = (const float*)d_in[14];
    const float* sw3 = (const float*)d_in[15];
    float* out = (float*)d_out;

    float *h,*xf,*eo;
    __half *qkvs,*xnh,*atth,*xfh,*h1h;
    __half *wqkvh,*woh,*ew13h,*ew2h;
    int *gath,*tileE;
    cudaGetSymbolAddress((void**)&h,    g_h);
    cudaGetSymbolAddress((void**)&xf,   g_xf);
    cudaGetSymbolAddress((void**)&eo,   g_eo);
    cudaGetSymbolAddress((void**)&qkvs, g_qkvs);
    cudaGetSymbolAddress((void**)&xnh,  g_xnh);
    cudaGetSymbolAddress((void**)&atth, g_atth);
    cudaGetSymbolAddress((void**)&xfh,  g_xfh);
    cudaGetSymbolAddress((void**)&h1h,  g_h1h);
    cudaGetSymbolAddress((void**)&wqkvh,g_wqkvh);
    cudaGetSymbolAddress((void**)&woh,  g_woh);
    cudaGetSymbolAddress((void**)&ew13h,g_ew13h);
    cudaGetSymbolAddress((void**)&ew2h, g_ew2h);
    cudaGetSymbolAddress((void**)&gath,  g_gather);
    cudaGetSymbolAddress((void**)&tileE, g_tileE);

    __half* qh = qkvs;
    __half* kh = qkvs + (long)NTOK*D_;
    __half* vh = qkvs + 2l*NTOK*D_;

    cudaFuncSetAttribute(hgemm_k<float,0>,  cudaFuncAttributeMaxDynamicSharedMemorySize, GEMM_SMEM);
    cudaFuncSetAttribute(hgemm_k<float,1>,  cudaFuncAttributeMaxDynamicSharedMemorySize, GEMM_SMEM);
    cudaFuncSetAttribute(hgemm_k<__half,3>, cudaFuncAttributeMaxDynamicSharedMemorySize, GEMM_SMEM);
    cudaFuncSetAttribute(hgemm_k<__half,4>, cudaFuncAttributeMaxDynamicSharedMemorySize, GEMM_SMEM);

    // 0: merged weight conversion
    cvtall_k<<<(22*M1Q)/256, 256>>>(
        (const float4*)wq, (const float4*)wk, (const float4*)wv,
        (const float4*)wo, (const float4*)sw1, (const float4*)sw2, (const float4*)sw3,
        (const float4*)ew1, (const float4*)ew2, (const float4*)ew3);
    // 1: moe init (incl. identity gather for shared tiles)
    moe_init_k<<<(AROWS + 255)/256, 256>>>();
    // 2: rmsnorm -> xnh
    rmsnorm_k<<<NTOK, 256>>>(x, anw, nullptr, xnh);
    // 3: QKV gemm + fused rope
    hgemm_k<__half,4><<<dim3(24,32), 256, GEMM_SMEM>>>(xnh, wqkvh, qkvs, nullptr, 1024, 3072,
                                                       nullptr, nullptr, 0, nullptr, fc, fs);
    // 4: flash attention
    flash_h_k<<<dim3(S_/64, B_*H_), 128>>>(qh, kh, vh, atth);
    // 5: wo projection + residual  (<- ncu -s 5)
    hgemm_k<float,1><<<dim3(8,32), 256, GEMM_SMEM>>>(atth, woh, h, x, 1024, 1024,
                                                     nullptr, nullptr, 0, nullptr, nullptr, nullptr);
    // 6: rmsnorm -> xf, xfh
    rmsnorm_k<<<NTOK, 256>>>(h, fnw, xf, xfh);
    // 7-9: routing
    gate_k<<<NTOK, 256>>>(xf, gw);
    offsets_k<<<1, 128>>>();
    scatter_k<<<NTOK/256, 256>>>();
    // 10: fused up GEMM (routed experts + shared as expert 8), silu-mul epilogue
    hgemm_k<__half,3><<<dim3(16,NT_ALL), 256, GEMM_SMEM>>>(xfh, ew13h, h1h, nullptr, 1024, 2048,
                                                           gath, tileE, 1024l*2048, gath, nullptr, nullptr);
    // 11: fused down GEMM
    hgemm_k<float,0><<<dim3(8,NT_ALL), 256, GEMM_SMEM>>>(h1h, ew2h, eo, nullptr, 1024, 1024,
                                                         nullptr, tileE, 1024l*1024, gath, nullptr, nullptr);
    // 12: combine (residual + shared + weighted experts)
    combine_k<<<(NTOK*D_)/256, 256>>>(out);
}